// round 10
// baseline (speedup 1.0000x reference)
#include <cuda_runtime.h>
#include <cuda_bf16.h>
#include <mma.h>
#include <math.h>

using namespace nvcuda;

#define N_NODES 100000
#define N_PAD   100096                 // 782 * 128
#define N_EDGES 1000000
#define FULL 0xFFFFFFFFu

// Scratch (device globals — no dynamic allocation allowed)
__device__ __align__(16) float g_dinv[N_NODES];              // wdeg accum -> dinv
__device__ __align__(16) float g_xw[(size_t)N_NODES * 128];
__device__ __align__(16) float g_agg[(size_t)N_PAD * 128];   // pad rows stay 0
// CSR by destination (col)
__device__ int   g_cnt[N_NODES];
__device__ int   g_off[N_NODES];
__device__ int   g_cur[N_NODES];
__device__ int   g_bsum[128];
__device__ int   g_src[N_EDGES];
__device__ float g_ewc[N_EDGES];        // premultiplied: dinv[src] * ew

// ---------------------------------------------------------------------------
// K0: zero counts, init weighted degree with self-loop weight 1
__global__ void k_zero() {
    int i = blockIdx.x * blockDim.x + threadIdx.x;
    if (i < N_NODES) { g_cnt[i] = 0; g_dinv[i] = 1.0f; }
}

// K1: histogram count + weighted degree in one pass
__global__ void k_hist(const int* __restrict__ ei, const float* __restrict__ ew) {
    int e = blockIdx.x * blockDim.x + threadIdx.x;
    if (e < N_EDGES) {
        int col = ei[N_EDGES + e];
        atomicAdd(&g_cnt[col], 1);
        atomicAdd(&g_dinv[col], ew[e]);
    }
}

// Scan phase 1: per-block (1024) exclusive scan of g_cnt -> g_off, totals -> g_bsum
__global__ void __launch_bounds__(1024) k_scan1() {
    __shared__ int wsum[32];
    int i = blockIdx.x * 1024 + threadIdx.x;
    int lane = threadIdx.x & 31, wid = threadIdx.x >> 5;
    int c = (i < N_NODES) ? g_cnt[i] : 0;
    int v = c;
    #pragma unroll
    for (int o = 1; o < 32; o <<= 1) {
        int t = __shfl_up_sync(FULL, v, o);
        if (lane >= o) v += t;
    }
    if (lane == 31) wsum[wid] = v;
    __syncthreads();
    if (wid == 0) {
        int s = wsum[lane];
        #pragma unroll
        for (int o = 1; o < 32; o <<= 1) {
            int t = __shfl_up_sync(FULL, s, o);
            if (lane >= o) s += t;
        }
        wsum[lane] = s;
    }
    __syncthreads();
    int base = (wid > 0) ? wsum[wid - 1] : 0;
    int incl = v + base;
    if (i < N_NODES) g_off[i] = incl - c;
    if (threadIdx.x == 1023) g_bsum[blockIdx.x] = incl;
}

// Scan phase 2: parallel exclusive scan of 98 block sums
__global__ void __launch_bounds__(128) k_scan2(int nb) {
    __shared__ int ws[4];
    int t = threadIdx.x, lane = t & 31, w = t >> 5;
    int c = (t < nb) ? g_bsum[t] : 0;
    int v = c;
    #pragma unroll
    for (int o = 1; o < 32; o <<= 1) {
        int x = __shfl_up_sync(FULL, v, o);
        if (lane >= o) v += x;
    }
    if (lane == 31) ws[w] = v;
    __syncthreads();
    int base = 0;
    #pragma unroll
    for (int k = 0; k < 4; k++) if (k < w) base += ws[k];
    if (t < nb) g_bsum[t] = v + base - c;
}

// Scan phase 3: finalize offsets + cursor + dinv = rsqrt(wdeg)
__global__ void k_scan3() {
    int i = blockIdx.x * blockDim.x + threadIdx.x;
    if (i < N_NODES) {
        int o = g_off[i] + g_bsum[i >> 10];
        g_off[i] = o;
        g_cur[i] = o;
        g_dinv[i] = rsqrtf(g_dinv[i]);   // wdeg >= 1 always (self-loop)
    }
}

// Fill CSR with src + premultiplied weight dinv[src]*ew  (dinv final here)
__global__ void k_csr(const int* __restrict__ ei, const float* __restrict__ ew) {
    int e = blockIdx.x * blockDim.x + threadIdx.x;
    if (e < N_EDGES) {
        int row = ei[e];
        int col = ei[N_EDGES + e];
        int pos = atomicAdd(&g_cur[col], 1);
        g_src[pos] = row;
        g_ewc[pos] = ew[e] * g_dinv[row];
    }
}

// xw = x@W (both convs). 8 nodes per 128-thread block.
__global__ void __launch_bounds__(128) k_xw(
    const float* __restrict__ user_x, const float* __restrict__ movie_x,
    const float* __restrict__ Wu, const float* __restrict__ Wm)
{
    int nb = blockIdx.x * 8;
    int j  = threadIdx.x;
    __shared__ float su[8 * 3];
    __shared__ float sv[8 * 18];

    if (j < 24) su[j] = user_x[(size_t)nb * 3 + j];
    for (int i = j; i < 144; i += 128) sv[i] = movie_x[(size_t)nb * 18 + i];

    float w[18];
    if (j < 64) {
        #pragma unroll
        for (int k = 0; k < 3; k++) w[k] = Wu[k * 64 + j];
    } else {
        int jj = j - 64;
        #pragma unroll
        for (int k = 0; k < 18; k++) w[k] = Wm[k * 64 + jj];
    }
    __syncthreads();

    #pragma unroll
    for (int nd = 0; nd < 8; nd++) {
        float acc = 0.0f;
        if (j < 64) {
            #pragma unroll
            for (int k = 0; k < 3; k++) acc = fmaf(su[nd * 3 + k], w[k], acc);
        } else {
            #pragma unroll
            for (int k = 0; k < 18; k++) acc = fmaf(sv[nd * 18 + k], w[k], acc);
        }
        g_xw[(size_t)(nb + nd) * 128 + j] = acc;
    }
}

// Aggregate: one warp per destination node, register accumulation, no atomics.
// out[n] = dc * ( dc*xw[n] + sum_e ewc_e * xw[src_e] ) + bias
__global__ void __launch_bounds__(256) k_agg(
    const float* __restrict__ bu, const float* __restrict__ bm)
{
    int node = (blockIdx.x * blockDim.x + threadIdx.x) >> 5;
    int lane = threadIdx.x & 31;
    if (node >= N_NODES) return;

    int off = g_off[node], cnt = g_cnt[node];
    float dc = g_dinv[node];

    float4 own = reinterpret_cast<const float4*>(g_xw + (size_t)node * 128)[lane];
    float4 acc;
    acc.x = dc * own.x; acc.y = dc * own.y; acc.z = dc * own.z; acc.w = dc * own.w;

    for (int base = 0; base < cnt; base += 32) {
        int rem = min(cnt - base, 32);
        int src = 0; float nrm = 0.0f;
        if (lane < rem) {
            int idx = off + base + lane;
            src = g_src[idx];
            nrm = g_ewc[idx];
        }
        int j = 0;
        for (; j + 8 <= rem; j += 8) {
            int   s[8]; float n[8]; float4 v[8];
            #pragma unroll
            for (int q = 0; q < 8; q++) {
                s[q] = __shfl_sync(FULL, src, j + q);
                n[q] = __shfl_sync(FULL, nrm, j + q);
            }
            #pragma unroll
            for (int q = 0; q < 8; q++)
                v[q] = reinterpret_cast<const float4*>(g_xw + (size_t)s[q] * 128)[lane];
            #pragma unroll
            for (int q = 0; q < 8; q++) {
                acc.x = fmaf(n[q], v[q].x, acc.x);
                acc.y = fmaf(n[q], v[q].y, acc.y);
                acc.z = fmaf(n[q], v[q].z, acc.z);
                acc.w = fmaf(n[q], v[q].w, acc.w);
            }
        }
        for (; j < rem; j++) {
            int sq = __shfl_sync(FULL, src, j);
            float nq = __shfl_sync(FULL, nrm, j);
            float4 vq = reinterpret_cast<const float4*>(g_xw + (size_t)sq * 128)[lane];
            acc.x = fmaf(nq, vq.x, acc.x); acc.y = fmaf(nq, vq.y, acc.y);
            acc.z = fmaf(nq, vq.z, acc.z); acc.w = fmaf(nq, vq.w, acc.w);
        }
    }

    float4 bias = (lane < 16) ? reinterpret_cast<const float4*>(bu)[lane]
                              : reinterpret_cast<const float4*>(bm)[lane - 16];
    float4 res;
    res.x = fmaf(dc, acc.x, bias.x);
    res.y = fmaf(dc, acc.y, bias.y);
    res.z = fmaf(dc, acc.z, bias.z);
    res.w = fmaf(dc, acc.w, bias.w);
    reinterpret_cast<float4*>(g_agg + (size_t)node * 128)[lane] = res;
}

// ---------------------------------------------------------------------------
// MLP via 3xBF16 tensor cores. Block tile: 128 nodes x 128 channels, K=128.
// 512 threads = 16 warps (4 x 4): warp tile 32x32 = 2x2 16x16 frags.
// hi/lo bf16 split once during staging (packed bf16x2 stores); pure-mma k-loop.

#define MLD 136   // bf16 smem leading dim (elements)
#define HLD 132   // float H leading dim (16B-aligned rows: 132*4 = 528)

extern __shared__ char s_mlp_raw[];

__device__ __forceinline__ void bf16_split2(float x, float y,
                                            __nv_bfloat162& hi, __nv_bfloat162& lo) {
    __nv_bfloat16 hx = __float2bfloat16_rn(x);
    __nv_bfloat16 hy = __float2bfloat16_rn(y);
    hi = __nv_bfloat162(hx, hy);
    lo = __nv_bfloat162(__float2bfloat16_rn(x - __bfloat162float(hx)),
                        __float2bfloat16_rn(y - __bfloat162float(hy)));
}

__global__ void __launch_bounds__(512) k_mlp_tc(
    const float* __restrict__ W1, const float* __restrict__ b1,
    const float* __restrict__ W2, const float* __restrict__ b2,
    float* __restrict__ out)
{
    __nv_bfloat16* aHi = reinterpret_cast<__nv_bfloat16*>(s_mlp_raw);
    __nv_bfloat16* aLo = aHi + 128 * MLD;
    __nv_bfloat16* bHi = reinterpret_cast<__nv_bfloat16*>(s_mlp_raw + 2 * 128 * MLD * 2);
    __nv_bfloat16* bLo = bHi + 128 * MLD;
    float* H = reinterpret_cast<float*>(s_mlp_raw);   // reuses A region (needs 128*HLD*4 <= 2*128*MLD*2)

    int tid  = threadIdx.x;
    int warp = tid >> 5;
    int lane = tid & 31;
    int wm   = warp >> 2;     // 0..3 -> 32-row band
    int wn   = warp & 3;      // 0..3 -> 32-col band
    int n0   = blockIdx.x * 128;

    // Stage A (g_agg tile) and B (W1) with bf16 hi/lo split, packed stores
    const float4* A4 = reinterpret_cast<const float4*>(g_agg + (size_t)n0 * 128);
    const float4* B4 = reinterpret_cast<const float4*>(W1);
    for (int i = tid; i < 128 * 32; i += 512) {
        int r = i >> 5, c4 = (i & 31) * 4;
        float4 va = A4[i];
        float4 vb = B4[i];
        int o = r * MLD + c4;
        __nv_bfloat162 h0, l0, h1, l1;
        bf16_split2(va.x, va.y, h0, l0);
        bf16_split2(va.z, va.w, h1, l1);
        *reinterpret_cast<__nv_bfloat162*>(aHi + o)     = h0;
        *reinterpret_cast<__nv_bfloat162*>(aHi + o + 2) = h1;
        *reinterpret_cast<__nv_bfloat162*>(aLo + o)     = l0;
        *reinterpret_cast<__nv_bfloat162*>(aLo + o + 2) = l1;
        bf16_split2(vb.x, vb.y, h0, l0);
        bf16_split2(vb.z, vb.w, h1, l1);
        *reinterpret_cast<__nv_bfloat162*>(bHi + o)     = h0;
        *reinterpret_cast<__nv_bfloat162*>(bHi + o + 2) = h1;
        *reinterpret_cast<__nv_bfloat162*>(bLo + o)     = l0;
        *reinterpret_cast<__nv_bfloat162*>(bLo + o + 2) = l1;
    }
    __syncthreads();

    wmma::fragment<wmma::accumulator, 16, 16, 16, float> acc[2][2];
    #pragma unroll
    for (int fm = 0; fm < 2; fm++)
        #pragma unroll
        for (int fn = 0; fn < 2; fn++)
            wmma::fill_fragment(acc[fm][fn], 0.0f);

    #pragma unroll
    for (int k0 = 0; k0 < 128; k0 += 16) {
        wmma::fragment<wmma::matrix_a, 16, 16, 16, __nv_bfloat16, wmma::row_major> ah[2], al[2];
        wmma::fragment<wmma::matrix_b, 16, 16, 16, __nv_bfloat16, wmma::row_major> bh[2], bl[2];
        #pragma unroll
        for (int fm = 0; fm < 2; fm++) {
            int ro = (wm * 32 + fm * 16) * MLD + k0;
            wmma::load_matrix_sync(ah[fm], aHi + ro, MLD);
            wmma::load_matrix_sync(al[fm], aLo + ro, MLD);
        }
        #pragma unroll
        for (int fn = 0; fn < 2; fn++) {
            int co = k0 * MLD + wn * 32 + fn * 16;
            wmma::load_matrix_sync(bh[fn], bHi + co, MLD);
            wmma::load_matrix_sync(bl[fn], bLo + co, MLD);
        }
        #pragma unroll
        for (int fm = 0; fm < 2; fm++)
            #pragma unroll
            for (int fn = 0; fn < 2; fn++) {
                wmma::mma_sync(acc[fm][fn], ah[fm], bl[fn], acc[fm][fn]);
                wmma::mma_sync(acc[fm][fn], al[fm], bh[fn], acc[fm][fn]);
                wmma::mma_sync(acc[fm][fn], ah[fm], bh[fn], acc[fm][fn]);
            }
    }
    __syncthreads();   // everyone done reading A before H overwrites it

    #pragma unroll
    for (int fm = 0; fm < 2; fm++)
        #pragma unroll
        for (int fn = 0; fn < 2; fn++)
            wmma::store_matrix_sync(H + (wm * 32 + fm * 16) * HLD + wn * 32 + fn * 16,
                                    acc[fm][fn], HLD, wmma::mem_row_major);
    __syncthreads();

    // Epilogue: warp per node (16 warps x 8 nodes), lanes sweep channels.
    float b1v[4], w2v[4];
    #pragma unroll
    for (int i = 0; i < 4; i++) {
        int c = lane + i * 32;
        b1v[i] = b1[c];
        w2v[i] = W2[c];
    }
    float b2v = b2[0];
    #pragma unroll
    for (int s = 0; s < 8; s++) {
        int n = warp * 8 + s;
        float p = 0.0f;
        #pragma unroll
        for (int i = 0; i < 4; i++) {
            float h = H[n * HLD + lane + i * 32] + b1v[i];
            p = fmaf(fmaxf(h, 0.0f), w2v[i], p);
        }
        #pragma unroll
        for (int off = 16; off > 0; off >>= 1)
            p += __shfl_xor_sync(FULL, p, off);
        int node = n0 + n;
        if (lane == 0 && node < N_NODES) out[node] = p + b2v;
    }
}

// ---------------------------------------------------------------------------
extern "C" void kernel_launch(void* const* d_in, const int* in_sizes, int n_in,
                              void* d_out, int out_size) {
    const float* user_x  = (const float*)d_in[0];
    const float* movie_x = (const float*)d_in[1];
    const int*   ei      = (const int*)d_in[2];   // int32 (JAX x64 disabled)
    const float* ea      = (const float*)d_in[3];
    const float* W_user  = (const float*)d_in[4];
    const float* b_user  = (const float*)d_in[5];
    const float* W_movie = (const float*)d_in[6];
    const float* b_movie = (const float*)d_in[7];
    const float* W1      = (const float*)d_in[8];
    const float* b1      = (const float*)d_in[9];
    const float* W2      = (const float*)d_in[10];
    const float* b2      = (const float*)d_in[11];
    float* out = (float*)d_out;

    const int nb_scan = (N_NODES + 1023) / 1024;  // 98
    const int mlp_smem = 4 * 128 * MLD * 2;       // 139,264 B

    static int smem_set = 0;
    if (!smem_set) {
        cudaFuncSetAttribute(k_mlp_tc, cudaFuncAttributeMaxDynamicSharedMemorySize, mlp_smem);
        smem_set = 1;
    }

    k_zero   <<<(N_NODES + 255) / 256, 256>>>();
    k_hist   <<<(N_EDGES + 255) / 256, 256>>>(ei, ea);
    k_scan1  <<<nb_scan, 1024>>>();
    k_scan2  <<<1, 128>>>(nb_scan);
    k_scan3  <<<(N_NODES + 255) / 256, 256>>>();
    k_csr    <<<(N_EDGES + 255) / 256, 256>>>(ei, ea);
    k_xw     <<<N_NODES / 8, 128>>>(user_x, movie_x, W_user, W_movie);
    k_agg    <<<(N_NODES * 32 + 255) / 256, 256>>>(b_user, b_movie);
    k_mlp_tc <<<N_PAD / 128, 512, mlp_smem>>>(W1, b1, W2, b2, out);
}

// round 11
// speedup vs baseline: 1.3282x; 1.3282x over previous
#include <cuda_runtime.h>
#include <cuda_bf16.h>
#include <mma.h>
#include <math.h>

using namespace nvcuda;

#define N_NODES 100000
#define N_PAD   100096                 // 782 * 128
#define N_EDGES 1000000
#define FULL 0xFFFFFFFFu

// Scratch (device globals — no dynamic allocation allowed)
__device__ __align__(16) float g_dinv[N_NODES];              // wdeg accum -> dinv
__device__ __align__(16) float g_xw[(size_t)N_NODES * 128];
__device__ __align__(16) float g_agg[(size_t)N_PAD * 128];   // pad rows stay 0
// CSR by destination (col)
__device__ int   g_cnt[N_NODES];
__device__ int   g_off[N_NODES];
__device__ int   g_cur[N_NODES];
__device__ int   g_bsum[128];
__device__ int   g_src[N_EDGES];
__device__ float g_ewc[N_EDGES];        // premultiplied: dinv[src] * ew

// ---------------------------------------------------------------------------
// K0: zero counts, init weighted degree with self-loop weight 1
__global__ void k_zero() {
    int i = blockIdx.x * blockDim.x + threadIdx.x;
    if (i < N_NODES) { g_cnt[i] = 0; g_dinv[i] = 1.0f; }
}

// K1: histogram count + weighted degree in one pass
__global__ void k_hist(const int* __restrict__ ei, const float* __restrict__ ew) {
    int e = blockIdx.x * blockDim.x + threadIdx.x;
    if (e < N_EDGES) {
        int col = ei[N_EDGES + e];
        atomicAdd(&g_cnt[col], 1);
        atomicAdd(&g_dinv[col], ew[e]);
    }
}

// Scan phase 1: per-block (1024) exclusive scan of g_cnt -> g_off, totals -> g_bsum
__global__ void __launch_bounds__(1024) k_scan1() {
    __shared__ int wsum[32];
    int i = blockIdx.x * 1024 + threadIdx.x;
    int lane = threadIdx.x & 31, wid = threadIdx.x >> 5;
    int c = (i < N_NODES) ? g_cnt[i] : 0;
    int v = c;
    #pragma unroll
    for (int o = 1; o < 32; o <<= 1) {
        int t = __shfl_up_sync(FULL, v, o);
        if (lane >= o) v += t;
    }
    if (lane == 31) wsum[wid] = v;
    __syncthreads();
    if (wid == 0) {
        int s = wsum[lane];
        #pragma unroll
        for (int o = 1; o < 32; o <<= 1) {
            int t = __shfl_up_sync(FULL, s, o);
            if (lane >= o) s += t;
        }
        wsum[lane] = s;
    }
    __syncthreads();
    int base = (wid > 0) ? wsum[wid - 1] : 0;
    int incl = v + base;
    if (i < N_NODES) g_off[i] = incl - c;
    if (threadIdx.x == 1023) g_bsum[blockIdx.x] = incl;
}

// Scan phase 2: parallel exclusive scan of 98 block sums
__global__ void __launch_bounds__(128) k_scan2(int nb) {
    __shared__ int ws[4];
    int t = threadIdx.x, lane = t & 31, w = t >> 5;
    int c = (t < nb) ? g_bsum[t] : 0;
    int v = c;
    #pragma unroll
    for (int o = 1; o < 32; o <<= 1) {
        int x = __shfl_up_sync(FULL, v, o);
        if (lane >= o) v += x;
    }
    if (lane == 31) ws[w] = v;
    __syncthreads();
    int base = 0;
    #pragma unroll
    for (int k = 0; k < 4; k++) if (k < w) base += ws[k];
    if (t < nb) g_bsum[t] = v + base - c;
}

// Scan phase 3: finalize offsets + cursor + dinv = rsqrt(wdeg)
__global__ void k_scan3() {
    int i = blockIdx.x * blockDim.x + threadIdx.x;
    if (i < N_NODES) {
        int o = g_off[i] + g_bsum[i >> 10];
        g_off[i] = o;
        g_cur[i] = o;
        g_dinv[i] = rsqrtf(g_dinv[i]);   // wdeg >= 1 always (self-loop)
    }
}

// Fill CSR with src + premultiplied weight dinv[src]*ew  (dinv final here)
__global__ void k_csr(const int* __restrict__ ei, const float* __restrict__ ew) {
    int e = blockIdx.x * blockDim.x + threadIdx.x;
    if (e < N_EDGES) {
        int row = ei[e];
        int col = ei[N_EDGES + e];
        int pos = atomicAdd(&g_cur[col], 1);
        g_src[pos] = row;
        g_ewc[pos] = ew[e] * g_dinv[row];
    }
}

// xw = x@W (both convs). 8 nodes per 128-thread block.
__global__ void __launch_bounds__(128) k_xw(
    const float* __restrict__ user_x, const float* __restrict__ movie_x,
    const float* __restrict__ Wu, const float* __restrict__ Wm)
{
    int nb = blockIdx.x * 8;
    int j  = threadIdx.x;
    __shared__ float su[8 * 3];
    __shared__ float sv[8 * 18];

    if (j < 24) su[j] = user_x[(size_t)nb * 3 + j];
    for (int i = j; i < 144; i += 128) sv[i] = movie_x[(size_t)nb * 18 + i];

    float w[18];
    if (j < 64) {
        #pragma unroll
        for (int k = 0; k < 3; k++) w[k] = Wu[k * 64 + j];
    } else {
        int jj = j - 64;
        #pragma unroll
        for (int k = 0; k < 18; k++) w[k] = Wm[k * 64 + jj];
    }
    __syncthreads();

    #pragma unroll
    for (int nd = 0; nd < 8; nd++) {
        float acc = 0.0f;
        if (j < 64) {
            #pragma unroll
            for (int k = 0; k < 3; k++) acc = fmaf(su[nd * 3 + k], w[k], acc);
        } else {
            #pragma unroll
            for (int k = 0; k < 18; k++) acc = fmaf(sv[nd * 18 + k], w[k], acc);
        }
        g_xw[(size_t)(nb + nd) * 128 + j] = acc;
    }
}

// Aggregate (R9 structure: unroll 4). One warp per destination node.
// out[n] = dc * ( dc*xw[n] + sum_e ewc_e * xw[src_e] ) + bias
__global__ void __launch_bounds__(256) k_agg(
    const float* __restrict__ bu, const float* __restrict__ bm)
{
    int node = (blockIdx.x * blockDim.x + threadIdx.x) >> 5;
    int lane = threadIdx.x & 31;
    if (node >= N_NODES) return;

    int off = g_off[node], cnt = g_cnt[node];
    float dc = g_dinv[node];

    float4 own = reinterpret_cast<const float4*>(g_xw + (size_t)node * 128)[lane];
    float4 acc;
    acc.x = dc * own.x; acc.y = dc * own.y; acc.z = dc * own.z; acc.w = dc * own.w;

    for (int base = 0; base < cnt; base += 32) {
        int rem = min(cnt - base, 32);
        int src = 0; float nrm = 0.0f;
        if (lane < rem) {
            int idx = off + base + lane;
            src = g_src[idx];
            nrm = g_ewc[idx];
        }
        int j = 0;
        for (; j + 4 <= rem; j += 4) {
            int s0 = __shfl_sync(FULL, src, j);
            int s1 = __shfl_sync(FULL, src, j + 1);
            int s2i = __shfl_sync(FULL, src, j + 2);
            int s3 = __shfl_sync(FULL, src, j + 3);
            float n0 = __shfl_sync(FULL, nrm, j);
            float n1 = __shfl_sync(FULL, nrm, j + 1);
            float n2 = __shfl_sync(FULL, nrm, j + 2);
            float n3 = __shfl_sync(FULL, nrm, j + 3);
            float4 v0 = reinterpret_cast<const float4*>(g_xw + (size_t)s0 * 128)[lane];
            float4 v1 = reinterpret_cast<const float4*>(g_xw + (size_t)s1 * 128)[lane];
            float4 v2 = reinterpret_cast<const float4*>(g_xw + (size_t)s2i * 128)[lane];
            float4 v3 = reinterpret_cast<const float4*>(g_xw + (size_t)s3 * 128)[lane];
            acc.x = fmaf(n0, v0.x, acc.x); acc.y = fmaf(n0, v0.y, acc.y);
            acc.z = fmaf(n0, v0.z, acc.z); acc.w = fmaf(n0, v0.w, acc.w);
            acc.x = fmaf(n1, v1.x, acc.x); acc.y = fmaf(n1, v1.y, acc.y);
            acc.z = fmaf(n1, v1.z, acc.z); acc.w = fmaf(n1, v1.w, acc.w);
            acc.x = fmaf(n2, v2.x, acc.x); acc.y = fmaf(n2, v2.y, acc.y);
            acc.z = fmaf(n2, v2.z, acc.z); acc.w = fmaf(n2, v2.w, acc.w);
            acc.x = fmaf(n3, v3.x, acc.x); acc.y = fmaf(n3, v3.y, acc.y);
            acc.z = fmaf(n3, v3.z, acc.z); acc.w = fmaf(n3, v3.w, acc.w);
        }
        for (; j < rem; j++) {
            int sq = __shfl_sync(FULL, src, j);
            float nq = __shfl_sync(FULL, nrm, j);
            float4 vq = reinterpret_cast<const float4*>(g_xw + (size_t)sq * 128)[lane];
            acc.x = fmaf(nq, vq.x, acc.x); acc.y = fmaf(nq, vq.y, acc.y);
            acc.z = fmaf(nq, vq.z, acc.z); acc.w = fmaf(nq, vq.w, acc.w);
        }
    }

    float4 bias = (lane < 16) ? reinterpret_cast<const float4*>(bu)[lane]
                              : reinterpret_cast<const float4*>(bm)[lane - 16];
    float4 res;
    res.x = fmaf(dc, acc.x, bias.x);
    res.y = fmaf(dc, acc.y, bias.y);
    res.z = fmaf(dc, acc.z, bias.z);
    res.w = fmaf(dc, acc.w, bias.w);
    reinterpret_cast<float4*>(g_agg + (size_t)node * 128)[lane] = res;
}

// ---------------------------------------------------------------------------
// MLP via 3xBF16 tensor cores (R9-measured version: 256 threads, 8 warps,
// warp tile 64x32 = 4x2 16x16 frags; hi/lo split once during staging).

#define MLD 136   // smem leading dim (elements), mult of 8

extern __shared__ char s_mlp_raw[];

__global__ void __launch_bounds__(256) k_mlp_tc(
    const float* __restrict__ W1, const float* __restrict__ b1,
    const float* __restrict__ W2, const float* __restrict__ b2,
    float* __restrict__ out)
{
    __nv_bfloat16* aHi = reinterpret_cast<__nv_bfloat16*>(s_mlp_raw);
    __nv_bfloat16* aLo = aHi + 128 * MLD;
    __nv_bfloat16* bHi = reinterpret_cast<__nv_bfloat16*>(s_mlp_raw + 2 * 128 * MLD * 2);
    __nv_bfloat16* bLo = bHi + 128 * MLD;
    float* H = reinterpret_cast<float*>(s_mlp_raw);   // reuses A region after k-loop

    int tid  = threadIdx.x;
    int warp = tid >> 5;
    int wm   = warp >> 2;     // 0..1  -> 64-row band
    int wn   = warp & 3;      // 0..3  -> 32-col band
    int n0   = blockIdx.x * 128;

    const float4* A4 = reinterpret_cast<const float4*>(g_agg + (size_t)n0 * 128);
    const float4* B4 = reinterpret_cast<const float4*>(W1);
    for (int i = tid; i < 128 * 32; i += 256) {
        int r = i >> 5, c4 = (i & 31) * 4;
        float4 va = A4[i];
        float4 vb = B4[i];
        int o = r * MLD + c4;
        float f;
        __nv_bfloat16 h;
        f = va.x; h = __float2bfloat16_rn(f); aHi[o+0] = h; aLo[o+0] = __float2bfloat16_rn(f - __bfloat162float(h));
        f = va.y; h = __float2bfloat16_rn(f); aHi[o+1] = h; aLo[o+1] = __float2bfloat16_rn(f - __bfloat162float(h));
        f = va.z; h = __float2bfloat16_rn(f); aHi[o+2] = h; aLo[o+2] = __float2bfloat16_rn(f - __bfloat162float(h));
        f = va.w; h = __float2bfloat16_rn(f); aHi[o+3] = h; aLo[o+3] = __float2bfloat16_rn(f - __bfloat162float(h));
        f = vb.x; h = __float2bfloat16_rn(f); bHi[o+0] = h; bLo[o+0] = __float2bfloat16_rn(f - __bfloat162float(h));
        f = vb.y; h = __float2bfloat16_rn(f); bHi[o+1] = h; bLo[o+1] = __float2bfloat16_rn(f - __bfloat162float(h));
        f = vb.z; h = __float2bfloat16_rn(f); bHi[o+2] = h; bLo[o+2] = __float2bfloat16_rn(f - __bfloat162float(h));
        f = vb.w; h = __float2bfloat16_rn(f); bHi[o+3] = h; bLo[o+3] = __float2bfloat16_rn(f - __bfloat162float(h));
    }
    __syncthreads();

    wmma::fragment<wmma::accumulator, 16, 16, 16, float> acc[4][2];
    #pragma unroll
    for (int fm = 0; fm < 4; fm++)
        #pragma unroll
        for (int fn = 0; fn < 2; fn++)
            wmma::fill_fragment(acc[fm][fn], 0.0f);

    #pragma unroll
    for (int k0 = 0; k0 < 128; k0 += 16) {
        wmma::fragment<wmma::matrix_a, 16, 16, 16, __nv_bfloat16, wmma::row_major> ah[4], al[4];
        wmma::fragment<wmma::matrix_b, 16, 16, 16, __nv_bfloat16, wmma::row_major> bh[2], bl[2];
        #pragma unroll
        for (int fm = 0; fm < 4; fm++) {
            int ro = (wm * 64 + fm * 16) * MLD + k0;
            wmma::load_matrix_sync(ah[fm], aHi + ro, MLD);
            wmma::load_matrix_sync(al[fm], aLo + ro, MLD);
        }
        #pragma unroll
        for (int fn = 0; fn < 2; fn++) {
            int co = k0 * MLD + wn * 32 + fn * 16;
            wmma::load_matrix_sync(bh[fn], bHi + co, MLD);
            wmma::load_matrix_sync(bl[fn], bLo + co, MLD);
        }
        #pragma unroll
        for (int fm = 0; fm < 4; fm++)
            #pragma unroll
            for (int fn = 0; fn < 2; fn++) {
                wmma::mma_sync(acc[fm][fn], ah[fm], bl[fn], acc[fm][fn]);
                wmma::mma_sync(acc[fm][fn], al[fm], bh[fn], acc[fm][fn]);
                wmma::mma_sync(acc[fm][fn], ah[fm], bh[fn], acc[fm][fn]);
            }
    }
    __syncthreads();   // all warps done reading A before H overwrites it

    #pragma unroll
    for (int fm = 0; fm < 4; fm++)
        #pragma unroll
        for (int fn = 0; fn < 2; fn++)
            wmma::store_matrix_sync(H + (wm * 64 + fm * 16) * MLD + wn * 32 + fn * 16,
                                    acc[fm][fn], MLD, wmma::mem_row_major);
    __syncthreads();

    // Epilogue: out[n] = sum_c relu(H[n][c] + b1[c]) * W2[c] + b2
    if (tid < 128) {
        int node = n0 + tid;
        if (node < N_NODES) {
            float p = 0.0f;
            #pragma unroll 8
            for (int c = 0; c < 128; c++) {
                float h = H[tid * MLD + c] + b1[c];
                p = fmaf(fmaxf(h, 0.0f), W2[c], p);
            }
            out[node] = p + b2[0];
        }
    }
}

// ---------------------------------------------------------------------------
extern "C" void kernel_launch(void* const* d_in, const int* in_sizes, int n_in,
                              void* d_out, int out_size) {
    const float* user_x  = (const float*)d_in[0];
    const float* movie_x = (const float*)d_in[1];
    const int*   ei      = (const int*)d_in[2];   // int32 (JAX x64 disabled)
    const float* ea      = (const float*)d_in[3];
    const float* W_user  = (const float*)d_in[4];
    const float* b_user  = (const float*)d_in[5];
    const float* W_movie = (const float*)d_in[6];
    const float* b_movie = (const float*)d_in[7];
    const float* W1      = (const float*)d_in[8];
    const float* b1      = (const float*)d_in[9];
    const float* W2      = (const float*)d_in[10];
    const float* b2      = (const float*)d_in[11];
    float* out = (float*)d_out;

    const int nb_scan = (N_NODES + 1023) / 1024;  // 98
    const int mlp_smem = 4 * 128 * MLD * 2;       // 139,264 B

    static int smem_set = 0;
    if (!smem_set) {
        cudaFuncSetAttribute(k_mlp_tc, cudaFuncAttributeMaxDynamicSharedMemorySize, mlp_smem);
        smem_set = 1;
    }

    k_zero   <<<(N_NODES + 255) / 256, 256>>>();
    k_hist   <<<(N_EDGES + 255) / 256, 256>>>(ei, ea);
    k_scan1  <<<nb_scan, 1024>>>();
    k_scan2  <<<1, 128>>>(nb_scan);
    k_scan3  <<<(N_NODES + 255) / 256, 256>>>();
    k_csr    <<<(N_EDGES + 255) / 256, 256>>>(ei, ea);
    k_xw     <<<N_NODES / 8, 128>>>(user_x, movie_x, W_user, W_movie);
    k_agg    <<<(N_NODES * 32 + 255) / 256, 256>>>(b_user, b_movie);
    k_mlp_tc <<<N_PAD / 128, 256, mlp_smem>>>(W1, b1, W2, b2, out);
}

// round 14
// speedup vs baseline: 1.5165x; 1.1418x over previous
#include <cuda_runtime.h>
#include <cuda_bf16.h>
#include <cuda_fp16.h>
#include <mma.h>
#include <math.h>

using namespace nvcuda;

#define N_NODES 100000
#define N_PAD   100096                 // 782 * 128
#define N_EDGES 1000000
#define FULL 0xFFFFFFFFu

// Scratch (device globals — no dynamic allocation allowed)
__device__ __align__(16) float  g_dinv[N_NODES];              // wdeg accum -> dinv
__device__ __align__(16) __half g_xw[(size_t)N_NODES * 128];  // fp16 transformed features
__device__ __align__(16) float  g_agg[(size_t)N_PAD * 128];   // pad rows stay 0
// CSR by destination (col)
__device__ int   g_cnt[N_NODES];
__device__ int   g_off[N_NODES];
__device__ int   g_cur[N_NODES];
__device__ int   g_bsum[128];
__device__ int   g_src[N_EDGES];
__device__ float g_ewc[N_EDGES];        // premultiplied: dinv[src] * ew

// ---------------------------------------------------------------------------
// K0: zero counts, init weighted degree with self-loop weight 1
__global__ void k_zero() {
    int i = blockIdx.x * blockDim.x + threadIdx.x;
    if (i < N_NODES) { g_cnt[i] = 0; g_dinv[i] = 1.0f; }
}

// K1: histogram count + weighted degree in one pass
__global__ void k_hist(const int* __restrict__ ei, const float* __restrict__ ew) {
    int e = blockIdx.x * blockDim.x + threadIdx.x;
    if (e < N_EDGES) {
        int col = ei[N_EDGES + e];
        atomicAdd(&g_cnt[col], 1);
        atomicAdd(&g_dinv[col], ew[e]);
    }
}

// Scan phase 1: per-block (1024) exclusive scan of g_cnt -> g_off, totals -> g_bsum
__global__ void __launch_bounds__(1024) k_scan1() {
    __shared__ int wsum[32];
    int i = blockIdx.x * 1024 + threadIdx.x;
    int lane = threadIdx.x & 31, wid = threadIdx.x >> 5;
    int c = (i < N_NODES) ? g_cnt[i] : 0;
    int v = c;
    #pragma unroll
    for (int o = 1; o < 32; o <<= 1) {
        int t = __shfl_up_sync(FULL, v, o);
        if (lane >= o) v += t;
    }
    if (lane == 31) wsum[wid] = v;
    __syncthreads();
    if (wid == 0) {
        int s = wsum[lane];
        #pragma unroll
        for (int o = 1; o < 32; o <<= 1) {
            int t = __shfl_up_sync(FULL, s, o);
            if (lane >= o) s += t;
        }
        wsum[lane] = s;
    }
    __syncthreads();
    int base = (wid > 0) ? wsum[wid - 1] : 0;
    int incl = v + base;
    if (i < N_NODES) g_off[i] = incl - c;
    if (threadIdx.x == 1023) g_bsum[blockIdx.x] = incl;
}

// Scan phase 2: parallel exclusive scan of 98 block sums
__global__ void __launch_bounds__(128) k_scan2(int nb) {
    __shared__ int ws[4];
    int t = threadIdx.x, lane = t & 31, w = t >> 5;
    int c = (t < nb) ? g_bsum[t] : 0;
    int v = c;
    #pragma unroll
    for (int o = 1; o < 32; o <<= 1) {
        int x = __shfl_up_sync(FULL, v, o);
        if (lane >= o) v += x;
    }
    if (lane == 31) ws[w] = v;
    __syncthreads();
    int base = 0;
    #pragma unroll
    for (int k = 0; k < 4; k++) if (k < w) base += ws[k];
    if (t < nb) g_bsum[t] = v + base - c;
}

// Scan phase 3: finalize offsets + cursor + dinv = rsqrt(wdeg)
__global__ void k_scan3() {
    int i = blockIdx.x * blockDim.x + threadIdx.x;
    if (i < N_NODES) {
        int o = g_off[i] + g_bsum[i >> 10];
        g_off[i] = o;
        g_cur[i] = o;
        g_dinv[i] = rsqrtf(g_dinv[i]);   // wdeg >= 1 always (self-loop)
    }
}

// Fill CSR with src + premultiplied weight dinv[src]*ew  (dinv final here)
__global__ void k_csr(const int* __restrict__ ei, const float* __restrict__ ew) {
    int e = blockIdx.x * blockDim.x + threadIdx.x;
    if (e < N_EDGES) {
        int row = ei[e];
        int col = ei[N_EDGES + e];
        int pos = atomicAdd(&g_cur[col], 1);
        g_src[pos] = row;
        g_ewc[pos] = ew[e] * g_dinv[row];
    }
}

// xw = x@W (both convs), stored fp16. 8 nodes per 128-thread block.
__global__ void __launch_bounds__(128) k_xw(
    const float* __restrict__ user_x, const float* __restrict__ movie_x,
    const float* __restrict__ Wu, const float* __restrict__ Wm)
{
    int nb = blockIdx.x * 8;
    int j  = threadIdx.x;
    __shared__ float su[8 * 3];
    __shared__ float sv[8 * 18];

    if (j < 24) su[j] = user_x[(size_t)nb * 3 + j];
    for (int i = j; i < 144; i += 128) sv[i] = movie_x[(size_t)nb * 18 + i];

    float w[18];
    if (j < 64) {
        #pragma unroll
        for (int k = 0; k < 3; k++) w[k] = Wu[k * 64 + j];
    } else {
        int jj = j - 64;
        #pragma unroll
        for (int k = 0; k < 18; k++) w[k] = Wm[k * 64 + jj];
    }
    __syncthreads();

    #pragma unroll
    for (int nd = 0; nd < 8; nd++) {
        float acc = 0.0f;
        if (j < 64) {
            #pragma unroll
            for (int k = 0; k < 3; k++) acc = fmaf(su[nd * 3 + k], w[k], acc);
        } else {
            #pragma unroll
            for (int k = 0; k < 18; k++) acc = fmaf(sv[nd * 18 + k], w[k], acc);
        }
        g_xw[(size_t)(nb + nd) * 128 + j] = __float2half_rn(acc);
    }
}

// Aggregate: one warp per destination node, unroll 4, fp16 gathers (8B/lane).
// out[n] = dc * ( dc*xw[n] + sum_e ewc_e * xw[src_e] ) + bias
__device__ __forceinline__ void h4_fma(float4& acc, float n, uint2 u) {
    float2 fa = __half22float2(*reinterpret_cast<__half2*>(&u.x));
    float2 fb = __half22float2(*reinterpret_cast<__half2*>(&u.y));
    acc.x = fmaf(n, fa.x, acc.x);
    acc.y = fmaf(n, fa.y, acc.y);
    acc.z = fmaf(n, fb.x, acc.z);
    acc.w = fmaf(n, fb.y, acc.w);
}

__global__ void __launch_bounds__(256) k_agg(
    const float* __restrict__ bu, const float* __restrict__ bm)
{
    int node = (blockIdx.x * blockDim.x + threadIdx.x) >> 5;
    int lane = threadIdx.x & 31;
    if (node >= N_NODES) return;

    int off = g_off[node], cnt = g_cnt[node];
    float dc = g_dinv[node];

    float4 acc = make_float4(0.f, 0.f, 0.f, 0.f);
    {
        uint2 u = reinterpret_cast<const uint2*>(g_xw + (size_t)node * 128)[lane];
        h4_fma(acc, dc, u);
    }

    for (int base = 0; base < cnt; base += 32) {
        int rem = min(cnt - base, 32);
        int src = 0; float nrm = 0.0f;
        if (lane < rem) {
            int idx = off + base + lane;
            src = g_src[idx];
            nrm = g_ewc[idx];
        }
        int j = 0;
        for (; j + 4 <= rem; j += 4) {
            int s0 = __shfl_sync(FULL, src, j);
            int s1 = __shfl_sync(FULL, src, j + 1);
            int s2i = __shfl_sync(FULL, src, j + 2);
            int s3 = __shfl_sync(FULL, src, j + 3);
            float n0 = __shfl_sync(FULL, nrm, j);
            float n1 = __shfl_sync(FULL, nrm, j + 1);
            float n2 = __shfl_sync(FULL, nrm, j + 2);
            float n3 = __shfl_sync(FULL, nrm, j + 3);
            uint2 u0 = reinterpret_cast<const uint2*>(g_xw + (size_t)s0 * 128)[lane];
            uint2 u1 = reinterpret_cast<const uint2*>(g_xw + (size_t)s1 * 128)[lane];
            uint2 u2 = reinterpret_cast<const uint2*>(g_xw + (size_t)s2i * 128)[lane];
            uint2 u3 = reinterpret_cast<const uint2*>(g_xw + (size_t)s3 * 128)[lane];
            h4_fma(acc, n0, u0);
            h4_fma(acc, n1, u1);
            h4_fma(acc, n2, u2);
            h4_fma(acc, n3, u3);
        }
        for (; j < rem; j++) {
            int sq = __shfl_sync(FULL, src, j);
            float nq = __shfl_sync(FULL, nrm, j);
            uint2 uq = reinterpret_cast<const uint2*>(g_xw + (size_t)sq * 128)[lane];
            h4_fma(acc, nq, uq);
        }
    }

    float4 bias = (lane < 16) ? reinterpret_cast<const float4*>(bu)[lane]
                              : reinterpret_cast<const float4*>(bm)[lane - 16];
    float4 res;
    res.x = fmaf(dc, acc.x, bias.x);
    res.y = fmaf(dc, acc.y, bias.y);
    res.z = fmaf(dc, acc.z, bias.z);
    res.w = fmaf(dc, acc.w, bias.w);
    reinterpret_cast<float4*>(g_agg + (size_t)node * 128)[lane] = res;
}

// ---------------------------------------------------------------------------
// MLP via 3xBF16 tensor cores (R11-measured version, unchanged).

#define MLD 136   // smem leading dim (elements), mult of 8

extern __shared__ char s_mlp_raw[];

__global__ void __launch_bounds__(256) k_mlp_tc(
    const float* __restrict__ W1, const float* __restrict__ b1,
    const float* __restrict__ W2, const float* __restrict__ b2,
    float* __restrict__ out)
{
    __nv_bfloat16* aHi = reinterpret_cast<__nv_bfloat16*>(s_mlp_raw);
    __nv_bfloat16* aLo = aHi + 128 * MLD;
    __nv_bfloat16* bHi = reinterpret_cast<__nv_bfloat16*>(s_mlp_raw + 2 * 128 * MLD * 2);
    __nv_bfloat16* bLo = bHi + 128 * MLD;
    float* H = reinterpret_cast<float*>(s_mlp_raw);   // reuses A region after k-loop

    int tid  = threadIdx.x;
    int warp = tid >> 5;
    int wm   = warp >> 2;     // 0..1  -> 64-row band
    int wn   = warp & 3;      // 0..3  -> 32-col band
    int n0   = blockIdx.x * 128;

    const float4* A4 = reinterpret_cast<const float4*>(g_agg + (size_t)n0 * 128);
    const float4* B4 = reinterpret_cast<const float4*>(W1);
    for (int i = tid; i < 128 * 32; i += 256) {
        int r = i >> 5, c4 = (i & 31) * 4;
        float4 va = A4[i];
        float4 vb = B4[i];
        int o = r * MLD + c4;
        float f;
        __nv_bfloat16 h;
        f = va.x; h = __float2bfloat16_rn(f); aHi[o+0] = h; aLo[o+0] = __float2bfloat16_rn(f - __bfloat162float(h));
        f = va.y; h = __float2bfloat16_rn(f); aHi[o+1] = h; aLo[o+1] = __float2bfloat16_rn(f - __bfloat162float(h));
        f = va.z; h = __float2bfloat16_rn(f); aHi[o+2] = h; aLo[o+2] = __float2bfloat16_rn(f - __bfloat162float(h));
        f = va.w; h = __float2bfloat16_rn(f); aHi[o+3] = h; aLo[o+3] = __float2bfloat16_rn(f - __bfloat162float(h));
        f = vb.x; h = __float2bfloat16_rn(f); bHi[o+0] = h; bLo[o+0] = __float2bfloat16_rn(f - __bfloat162float(h));
        f = vb.y; h = __float2bfloat16_rn(f); bHi[o+1] = h; bLo[o+1] = __float2bfloat16_rn(f - __bfloat162float(h));
        f = vb.z; h = __float2bfloat16_rn(f); bHi[o+2] = h; bLo[o+2] = __float2bfloat16_rn(f - __bfloat162float(h));
        f = vb.w; h = __float2bfloat16_rn(f); bHi[o+3] = h; bLo[o+3] = __float2bfloat16_rn(f - __bfloat162float(h));
    }
    __syncthreads();

    wmma::fragment<wmma::accumulator, 16, 16, 16, float> acc[4][2];
    #pragma unroll
    for (int fm = 0; fm < 4; fm++)
        #pragma unroll
        for (int fn = 0; fn < 2; fn++)
            wmma::fill_fragment(acc[fm][fn], 0.0f);

    #pragma unroll
    for (int k0 = 0; k0 < 128; k0 += 16) {
        wmma::fragment<wmma::matrix_a, 16, 16, 16, __nv_bfloat16, wmma::row_major> ah[4], al[4];
        wmma::fragment<wmma::matrix_b, 16, 16, 16, __nv_bfloat16, wmma::row_major> bh[2], bl[2];
        #pragma unroll
        for (int fm = 0; fm < 4; fm++) {
            int ro = (wm * 64 + fm * 16) * MLD + k0;
            wmma::load_matrix_sync(ah[fm], aHi + ro, MLD);
            wmma::load_matrix_sync(al[fm], aLo + ro, MLD);
        }
        #pragma unroll
        for (int fn = 0; fn < 2; fn++) {
            int co = k0 * MLD + wn * 32 + fn * 16;
            wmma::load_matrix_sync(bh[fn], bHi + co, MLD);
            wmma::load_matrix_sync(bl[fn], bLo + co, MLD);
        }
        #pragma unroll
        for (int fm = 0; fm < 4; fm++)
            #pragma unroll
            for (int fn = 0; fn < 2; fn++) {
                wmma::mma_sync(acc[fm][fn], ah[fm], bl[fn], acc[fm][fn]);
                wmma::mma_sync(acc[fm][fn], al[fm], bh[fn], acc[fm][fn]);
                wmma::mma_sync(acc[fm][fn], ah[fm], bh[fn], acc[fm][fn]);
            }
    }
    __syncthreads();   // all warps done reading A before H overwrites it

    #pragma unroll
    for (int fm = 0; fm < 4; fm++)
        #pragma unroll
        for (int fn = 0; fn < 2; fn++)
            wmma::store_matrix_sync(H + (wm * 64 + fm * 16) * MLD + wn * 32 + fn * 16,
                                    acc[fm][fn], MLD, wmma::mem_row_major);
    __syncthreads();

    // Epilogue: out[n] = sum_c relu(H[n][c] + b1[c]) * W2[c] + b2
    if (tid < 128) {
        int node = n0 + tid;
        if (node < N_NODES) {
            float p = 0.0f;
            #pragma unroll 8
            for (int c = 0; c < 128; c++) {
                float h = H[tid * MLD + c] + b1[c];
                p = fmaf(fmaxf(h, 0.0f), W2[c], p);
            }
            out[node] = p + b2[0];
        }
    }
}

// ---------------------------------------------------------------------------
extern "C" void kernel_launch(void* const* d_in, const int* in_sizes, int n_in,
                              void* d_out, int out_size) {
    const float* user_x  = (const float*)d_in[0];
    const float* movie_x = (const float*)d_in[1];
    const int*   ei      = (const int*)d_in[2];   // int32 (JAX x64 disabled)
    const float* ea      = (const float*)d_in[3];
    const float* W_user  = (const float*)d_in[4];
    const float* b_user  = (const float*)d_in[5];
    const float* W_movie = (const float*)d_in[6];
    const float* b_movie = (const float*)d_in[7];
    const float* W1      = (const float*)d_in[8];
    const float* b1      = (const float*)d_in[9];
    const float* W2      = (const float*)d_in[10];
    const float* b2      = (const float*)d_in[11];
    float* out = (float*)d_out;

    const int nb_scan = (N_NODES + 1023) / 1024;  // 98
    const int mlp_smem = 4 * 128 * MLD * 2;       // 139,264 B

    static int smem_set = 0;
    if (!smem_set) {
        cudaFuncSetAttribute(k_mlp_tc, cudaFuncAttributeMaxDynamicSharedMemorySize, mlp_smem);
        smem_set = 1;
    }

    k_zero   <<<(N_NODES + 255) / 256, 256>>>();
    k_hist   <<<(N_EDGES + 255) / 256, 256>>>(ei, ea);
    k_scan1  <<<nb_scan, 1024>>>();
    k_scan2  <<<1, 128>>>(nb_scan);
    k_scan3  <<<(N_NODES + 255) / 256, 256>>>();
    k_csr    <<<(N_EDGES + 255) / 256, 256>>>(ei, ea);
    k_xw     <<<N_NODES / 8, 128>>>(user_x, movie_x, W_user, W_movie);
    k_agg    <<<(N_NODES * 32 + 255) / 256, 256>>>(b_user, b_movie);
    k_mlp_tc <<<N_PAD / 128, 256, mlp_smem>>>(W1, b1, W2, b2, out);
}

// round 17
// speedup vs baseline: 1.7546x; 1.1570x over previous
#include <cuda_runtime.h>
#include <cuda_bf16.h>
#include <cuda_fp16.h>
#include <mma.h>
#include <math.h>
#include <cstdint>

using namespace nvcuda;

#define N_NODES 100000
#define N_PAD   100096                 // 782 * 128
#define N_EDGES 1000000
#define FULL 0xFFFFFFFFu

// Scratch (device globals — no dynamic allocation allowed)
__device__ __align__(16) float  g_dinv[N_NODES];              // wdeg accum -> dinv
__device__ __align__(16) __half g_xw[(size_t)N_NODES * 128];  // fp16 transformed features
// Aggregated conv output, pre-split to bf16 hi/lo (pad rows stay 0)
__device__ __align__(16) __nv_bfloat16 g_aggHi[(size_t)N_PAD * 128];
__device__ __align__(16) __nv_bfloat16 g_aggLo[(size_t)N_PAD * 128];
// W1 pre-split to bf16 hi/lo (128x128)
__device__ __align__(16) __nv_bfloat16 g_w1Hi[128 * 128];
__device__ __align__(16) __nv_bfloat16 g_w1Lo[128 * 128];
// CSR by destination (col)
__device__ int   g_cnt[N_NODES];
__device__ int   g_off[N_NODES];
__device__ int   g_cur[N_NODES];
__device__ int   g_bsum[128];
__device__ int   g_src[N_EDGES];
__device__ float g_ewc[N_EDGES];        // premultiplied: dinv[src] * ew

__device__ __forceinline__ void bf16_split(float x, __nv_bfloat16& hi, __nv_bfloat16& lo) {
    hi = __float2bfloat16_rn(x);
    lo = __float2bfloat16_rn(x - __bfloat162float(hi));
}

// ---------------------------------------------------------------------------
// K0: zero counts, init weighted degree, and pre-split W1 into bf16 hi/lo
__global__ void k_zero(const float* __restrict__ W1) {
    int i = blockIdx.x * blockDim.x + threadIdx.x;
    if (i < N_NODES) { g_cnt[i] = 0; g_dinv[i] = 1.0f; }
    if (i < 128 * 128) {
        bf16_split(W1[i], g_w1Hi[i], g_w1Lo[i]);
    }
}

// K1: histogram count + weighted degree in one pass
__global__ void k_hist(const int* __restrict__ ei, const float* __restrict__ ew) {
    int e = blockIdx.x * blockDim.x + threadIdx.x;
    if (e < N_EDGES) {
        int col = ei[N_EDGES + e];
        atomicAdd(&g_cnt[col], 1);
        atomicAdd(&g_dinv[col], ew[e]);
    }
}

// Scan phase 1: per-block (1024) exclusive scan of g_cnt -> g_off, totals -> g_bsum
__global__ void __launch_bounds__(1024) k_scan1() {
    __shared__ int wsum[32];
    int i = blockIdx.x * 1024 + threadIdx.x;
    int lane = threadIdx.x & 31, wid = threadIdx.x >> 5;
    int c = (i < N_NODES) ? g_cnt[i] : 0;
    int v = c;
    #pragma unroll
    for (int o = 1; o < 32; o <<= 1) {
        int t = __shfl_up_sync(FULL, v, o);
        if (lane >= o) v += t;
    }
    if (lane == 31) wsum[wid] = v;
    __syncthreads();
    if (wid == 0) {
        int s = wsum[lane];
        #pragma unroll
        for (int o = 1; o < 32; o <<= 1) {
            int t = __shfl_up_sync(FULL, s, o);
            if (lane >= o) s += t;
        }
        wsum[lane] = s;
    }
    __syncthreads();
    int base = (wid > 0) ? wsum[wid - 1] : 0;
    int incl = v + base;
    if (i < N_NODES) g_off[i] = incl - c;
    if (threadIdx.x == 1023) g_bsum[blockIdx.x] = incl;
}

// Scan phase 2: parallel exclusive scan of 98 block sums
__global__ void __launch_bounds__(128) k_scan2(int nb) {
    __shared__ int ws[4];
    int t = threadIdx.x, lane = t & 31, w = t >> 5;
    int c = (t < nb) ? g_bsum[t] : 0;
    int v = c;
    #pragma unroll
    for (int o = 1; o < 32; o <<= 1) {
        int x = __shfl_up_sync(FULL, v, o);
        if (lane >= o) v += x;
    }
    if (lane == 31) ws[w] = v;
    __syncthreads();
    int base = 0;
    #pragma unroll
    for (int k = 0; k < 4; k++) if (k < w) base += ws[k];
    if (t < nb) g_bsum[t] = v + base - c;
}

// Scan phase 3: finalize offsets + cursor + dinv = rsqrt(wdeg)
__global__ void k_scan3() {
    int i = blockIdx.x * blockDim.x + threadIdx.x;
    if (i < N_NODES) {
        int o = g_off[i] + g_bsum[i >> 10];
        g_off[i] = o;
        g_cur[i] = o;
        g_dinv[i] = rsqrtf(g_dinv[i]);   // wdeg >= 1 always (self-loop)
    }
}

// Fill CSR with src + premultiplied weight dinv[src]*ew
__global__ void k_csr(const int* __restrict__ ei, const float* __restrict__ ew) {
    int e = blockIdx.x * blockDim.x + threadIdx.x;
    if (e < N_EDGES) {
        int row = ei[e];
        int col = ei[N_EDGES + e];
        int pos = atomicAdd(&g_cur[col], 1);
        g_src[pos] = row;
        g_ewc[pos] = ew[e] * g_dinv[row];
    }
}

// xw = x@W (both convs), stored fp16. 8 nodes per 128-thread block.
__global__ void __launch_bounds__(128) k_xw(
    const float* __restrict__ user_x, const float* __restrict__ movie_x,
    const float* __restrict__ Wu, const float* __restrict__ Wm)
{
    int nb = blockIdx.x * 8;
    int j  = threadIdx.x;
    __shared__ float su[8 * 3];
    __shared__ float sv[8 * 18];

    if (j < 24) su[j] = user_x[(size_t)nb * 3 + j];
    for (int i = j; i < 144; i += 128) sv[i] = movie_x[(size_t)nb * 18 + i];

    float w[18];
    if (j < 64) {
        #pragma unroll
        for (int k = 0; k < 3; k++) w[k] = Wu[k * 64 + j];
    } else {
        int jj = j - 64;
        #pragma unroll
        for (int k = 0; k < 18; k++) w[k] = Wm[k * 64 + jj];
    }
    __syncthreads();

    #pragma unroll
    for (int nd = 0; nd < 8; nd++) {
        float acc = 0.0f;
        if (j < 64) {
            #pragma unroll
            for (int k = 0; k < 3; k++) acc = fmaf(su[nd * 3 + k], w[k], acc);
        } else {
            #pragma unroll
            for (int k = 0; k < 18; k++) acc = fmaf(sv[nd * 18 + k], w[k], acc);
        }
        g_xw[(size_t)(nb + nd) * 128 + j] = __float2half_rn(acc);
    }
}

// Aggregate: one warp per destination node, unroll 4, fp16 gathers (8B/lane).
// Result written pre-split to bf16 hi/lo for the MLP GEMM.
__device__ __forceinline__ void h4_fma(float4& acc, float n, uint2 u) {
    float2 fa = __half22float2(*reinterpret_cast<__half2*>(&u.x));
    float2 fb = __half22float2(*reinterpret_cast<__half2*>(&u.y));
    acc.x = fmaf(n, fa.x, acc.x);
    acc.y = fmaf(n, fa.y, acc.y);
    acc.z = fmaf(n, fb.x, acc.z);
    acc.w = fmaf(n, fb.y, acc.w);
}

__device__ __forceinline__ unsigned pack_bf162(__nv_bfloat16 a, __nv_bfloat16 b) {
    __nv_bfloat162 p(a, b);
    return *reinterpret_cast<unsigned*>(&p);
}

__global__ void __launch_bounds__(256) k_agg(
    const float* __restrict__ bu, const float* __restrict__ bm)
{
    int node = (blockIdx.x * blockDim.x + threadIdx.x) >> 5;
    int lane = threadIdx.x & 31;
    if (node >= N_NODES) return;

    int off = g_off[node], cnt = g_cnt[node];
    float dc = g_dinv[node];

    float4 acc = make_float4(0.f, 0.f, 0.f, 0.f);
    {
        uint2 u = reinterpret_cast<const uint2*>(g_xw + (size_t)node * 128)[lane];
        h4_fma(acc, dc, u);
    }

    for (int base = 0; base < cnt; base += 32) {
        int rem = min(cnt - base, 32);
        int src = 0; float nrm = 0.0f;
        if (lane < rem) {
            int idx = off + base + lane;
            src = g_src[idx];
            nrm = g_ewc[idx];
        }
        int j = 0;
        for (; j + 4 <= rem; j += 4) {
            int s0 = __shfl_sync(FULL, src, j);
            int s1 = __shfl_sync(FULL, src, j + 1);
            int s2i = __shfl_sync(FULL, src, j + 2);
            int s3 = __shfl_sync(FULL, src, j + 3);
            float n0 = __shfl_sync(FULL, nrm, j);
            float n1 = __shfl_sync(FULL, nrm, j + 1);
            float n2 = __shfl_sync(FULL, nrm, j + 2);
            float n3 = __shfl_sync(FULL, nrm, j + 3);
            uint2 u0 = reinterpret_cast<const uint2*>(g_xw + (size_t)s0 * 128)[lane];
            uint2 u1 = reinterpret_cast<const uint2*>(g_xw + (size_t)s1 * 128)[lane];
            uint2 u2 = reinterpret_cast<const uint2*>(g_xw + (size_t)s2i * 128)[lane];
            uint2 u3 = reinterpret_cast<const uint2*>(g_xw + (size_t)s3 * 128)[lane];
            h4_fma(acc, n0, u0);
            h4_fma(acc, n1, u1);
            h4_fma(acc, n2, u2);
            h4_fma(acc, n3, u3);
        }
        for (; j < rem; j++) {
            int sq = __shfl_sync(FULL, src, j);
            float nq = __shfl_sync(FULL, nrm, j);
            uint2 uq = reinterpret_cast<const uint2*>(g_xw + (size_t)sq * 128)[lane];
            h4_fma(acc, nq, uq);
        }
    }

    float4 bias = (lane < 16) ? reinterpret_cast<const float4*>(bu)[lane]
                              : reinterpret_cast<const float4*>(bm)[lane - 16];
    float4 res;
    res.x = fmaf(dc, acc.x, bias.x);
    res.y = fmaf(dc, acc.y, bias.y);
    res.z = fmaf(dc, acc.z, bias.z);
    res.w = fmaf(dc, acc.w, bias.w);

    // Split to bf16 hi/lo, packed 8B stores
    __nv_bfloat16 hx, lx, hy, ly, hz, lz, hw, lw;
    bf16_split(res.x, hx, lx);
    bf16_split(res.y, hy, ly);
    bf16_split(res.z, hz, lz);
    bf16_split(res.w, hw, lw);
    uint2 uh, ul;
    uh.x = pack_bf162(hx, hy); uh.y = pack_bf162(hz, hw);
    ul.x = pack_bf162(lx, ly); ul.y = pack_bf162(lz, lw);
    reinterpret_cast<uint2*>(g_aggHi + (size_t)node * 128)[lane] = uh;
    reinterpret_cast<uint2*>(g_aggLo + (size_t)node * 128)[lane] = ul;
}

// ---------------------------------------------------------------------------
// MLP via 3xBF16 tensor cores. GEMM core identical to R11/R14-measured version;
// staging is a pure uint4 copy (operands pre-split), epilogue warp-per-node.

#define MLD 136   // bf16 smem leading dim (elements)
#define HLD 132   // fp32 H leading dim (528 B rows, 16B-aligned)

extern __shared__ char s_mlp_raw[];

__global__ void __launch_bounds__(256) k_mlp_tc(
    const float* __restrict__ b1,
    const float* __restrict__ W2, const float* __restrict__ b2,
    float* __restrict__ out)
{
    __nv_bfloat16* aHi = reinterpret_cast<__nv_bfloat16*>(s_mlp_raw);
    __nv_bfloat16* aLo = aHi + 128 * MLD;
    __nv_bfloat16* bHi = reinterpret_cast<__nv_bfloat16*>(s_mlp_raw + 2 * 128 * MLD * 2);
    __nv_bfloat16* bLo = bHi + 128 * MLD;
    float* H = reinterpret_cast<float*>(s_mlp_raw);   // reuses A region (128*HLD*4 = 67584 <= 69632)

    int tid  = threadIdx.x;
    int warp = tid >> 5;
    int lane = tid & 31;
    int wm   = warp >> 2;     // 0..1  -> 64-row band
    int wn   = warp & 3;      // 0..3  -> 32-col band
    int n0   = blockIdx.x * 128;

    // Stage: pure vectorized copies (no conversion). Row = 128 bf16 = 16 uint4.
    const uint4* Ah4 = reinterpret_cast<const uint4*>(g_aggHi + (size_t)n0 * 128);
    const uint4* Al4 = reinterpret_cast<const uint4*>(g_aggLo + (size_t)n0 * 128);
    const uint4* Bh4 = reinterpret_cast<const uint4*>(g_w1Hi);
    const uint4* Bl4 = reinterpret_cast<const uint4*>(g_w1Lo);
    for (int i = tid; i < 128 * 16; i += 256) {
        int r = i >> 4, c = (i & 15) * 8;           // c in bf16 elements
        int o = r * MLD + c;
        *reinterpret_cast<uint4*>(aHi + o) = Ah4[i];
        *reinterpret_cast<uint4*>(aLo + o) = Al4[i];
        *reinterpret_cast<uint4*>(bHi + o) = Bh4[i];
        *reinterpret_cast<uint4*>(bLo + o) = Bl4[i];
    }
    __syncthreads();

    wmma::fragment<wmma::accumulator, 16, 16, 16, float> acc[4][2];
    #pragma unroll
    for (int fm = 0; fm < 4; fm++)
        #pragma unroll
        for (int fn = 0; fn < 2; fn++)
            wmma::fill_fragment(acc[fm][fn], 0.0f);

    #pragma unroll
    for (int k0 = 0; k0 < 128; k0 += 16) {
        wmma::fragment<wmma::matrix_a, 16, 16, 16, __nv_bfloat16, wmma::row_major> ah[4], al[4];
        wmma::fragment<wmma::matrix_b, 16, 16, 16, __nv_bfloat16, wmma::row_major> bh[2], bl[2];
        #pragma unroll
        for (int fm = 0; fm < 4; fm++) {
            int ro = (wm * 64 + fm * 16) * MLD + k0;
            wmma::load_matrix_sync(ah[fm], aHi + ro, MLD);
            wmma::load_matrix_sync(al[fm], aLo + ro, MLD);
        }
        #pragma unroll
        for (int fn = 0; fn < 2; fn++) {
            int co = k0 * MLD + wn * 32 + fn * 16;
            wmma::load_matrix_sync(bh[fn], bHi + co, MLD);
            wmma::load_matrix_sync(bl[fn], bLo + co, MLD);
        }
        #pragma unroll
        for (int fm = 0; fm < 4; fm++)
            #pragma unroll
            for (int fn = 0; fn < 2; fn++) {
                wmma::mma_sync(acc[fm][fn], ah[fm], bl[fn], acc[fm][fn]);
                wmma::mma_sync(acc[fm][fn], al[fm], bh[fn], acc[fm][fn]);
                wmma::mma_sync(acc[fm][fn], ah[fm], bh[fn], acc[fm][fn]);
            }
    }
    __syncthreads();   // all warps done reading A before H overwrites it

    #pragma unroll
    for (int fm = 0; fm < 4; fm++)
        #pragma unroll
        for (int fn = 0; fn < 2; fn++)
            wmma::store_matrix_sync(H + (wm * 64 + fm * 16) * HLD + wn * 32 + fn * 16,
                                    acc[fm][fn], HLD, wmma::mem_row_major);
    __syncthreads();

    // Epilogue: warp per node (8 warps x 16 nodes), lanes sweep channels
    // (contiguous within warp -> conflict-free LDS).
    float b1v[4], w2v[4];
    #pragma unroll
    for (int i = 0; i < 4; i++) {
        int c = lane + i * 32;
        b1v[i] = b1[c];
        w2v[i] = W2[c];
    }
    float b2v = b2[0];
    #pragma unroll
    for (int s = 0; s < 16; s++) {
        int n = warp * 16 + s;
        float p = 0.0f;
        #pragma unroll
        for (int i = 0; i < 4; i++) {
            float h = H[n * HLD + lane + i * 32] + b1v[i];
            p = fmaf(fmaxf(h, 0.0f), w2v[i], p);
        }
        #pragma unroll
        for (int off = 16; off > 0; off >>= 1)
            p += __shfl_xor_sync(FULL, p, off);
        int node = n0 + n;
        if (lane == 0 && node < N_NODES) out[node] = p + b2v;
    }
}

// ---------------------------------------------------------------------------
extern "C" void kernel_launch(void* const* d_in, const int* in_sizes, int n_in,
                              void* d_out, int out_size) {
    const float* user_x  = (const float*)d_in[0];
    const float* movie_x = (const float*)d_in[1];
    const int*   ei      = (const int*)d_in[2];   // int32 (JAX x64 disabled)
    const float* ea      = (const float*)d_in[3];
    const float* W_user  = (const float*)d_in[4];
    const float* b_user  = (const float*)d_in[5];
    const float* W_movie = (const float*)d_in[6];
    const float* b_movie = (const float*)d_in[7];
    const float* W1      = (const float*)d_in[8];
    const float* b1      = (const float*)d_in[9];
    const float* W2      = (const float*)d_in[10];
    const float* b2      = (const float*)d_in[11];
    float* out = (float*)d_out;

    const int nb_scan = (N_NODES + 1023) / 1024;  // 98
    const int mlp_smem = 4 * 128 * MLD * 2;       // 139,264 B

    static int smem_set = 0;
    if (!smem_set) {
        cudaFuncSetAttribute(k_mlp_tc, cudaFuncAttributeMaxDynamicSharedMemorySize, mlp_smem);
        smem_set = 1;
    }

    k_zero   <<<(N_NODES + 255) / 256, 256>>>(W1);
    k_hist   <<<(N_EDGES + 255) / 256, 256>>>(ei, ea);
    k_scan1  <<<nb_scan, 1024>>>();
    k_scan2  <<<1, 128>>>(nb_scan);
    k_scan3  <<<(N_NODES + 255) / 256, 256>>>();
    k_csr    <<<(N_EDGES + 255) / 256, 256>>>(ei, ea);
    k_xw     <<<N_NODES / 8, 128>>>(user_x, movie_x, W_user, W_movie);
    k_agg    <<<(N_NODES * 32 + 255) / 256, 256>>>(b_user, b_movie);
    k_mlp_tc <<<N_PAD / 128, 256, mlp_smem>>>(b1, W2, b2, out);
}